// round 16
// baseline (speedup 1.0000x reference)
#include <cuda_runtime.h>
#include <cuda_bf16.h>
#include <math.h>

typedef unsigned int u32;
typedef unsigned short u16;
typedef unsigned char u8;
typedef unsigned long long u64;
typedef unsigned long long ull;

#define N_SEQ 4096
#define M_SEQ 1024
#define DIMC  512
#define INNER 512
#define HEADS 8
#define GROUPS 8

// ---------------- warp-MMA helpers -------------------------------------------
__device__ __forceinline__ u32 smem_u32(const void* p) {
    u32 a;
    asm("{ .reg .u64 t; cvta.to.shared.u64 t, %1; cvt.u32.u64 %0, t; }" : "=r"(a) : "l"(p));
    return a;
}
__device__ __forceinline__ float ex2f(float x) {
    float r; asm("ex2.approx.ftz.f32 %0, %1;" : "=f"(r) : "f"(x)); return r;
}
__device__ __forceinline__ void ldsm_x4(u32 addr, u32& r0, u32& r1, u32& r2, u32& r3) {
    asm volatile("ldmatrix.sync.aligned.m8n8.x4.shared.b16 {%0,%1,%2,%3}, [%4];"
        : "=r"(r0), "=r"(r1), "=r"(r2), "=r"(r3) : "r"(addr));
}
__device__ __forceinline__ void ldsm_x2(u32 addr, u32& r0, u32& r1) {
    asm volatile("ldmatrix.sync.aligned.m8n8.x2.shared.b16 {%0,%1}, [%2];"
        : "=r"(r0), "=r"(r1) : "r"(addr));
}
__device__ __forceinline__ void ldsm_x2_t(u32 addr, u32& r0, u32& r1) {
    asm volatile("ldmatrix.sync.aligned.m8n8.x2.trans.shared.b16 {%0,%1}, [%2];"
        : "=r"(r0), "=r"(r1) : "r"(addr));
}
__device__ __forceinline__ void mma16816(float* c, u32 a0, u32 a1, u32 a2, u32 a3,
                                         u32 b0, u32 b1) {
    asm volatile(
        "mma.sync.aligned.m16n8k16.row.col.f32.bf16.bf16.f32 "
        "{%0,%1,%2,%3}, {%4,%5,%6,%7}, {%8,%9}, {%0,%1,%2,%3};"
        : "+f"(c[0]), "+f"(c[1]), "+f"(c[2]), "+f"(c[3])
        : "r"(a0), "r"(a1), "r"(a2), "r"(a3), "r"(b0), "r"(b1));
}
__device__ __forceinline__ u32 pack_bf16(float a, float b) {
    return ((u32)__bfloat16_as_ushort(__float2bfloat16(b)) << 16) |
           (u32)__bfloat16_as_ushort(__float2bfloat16(a));
}
__device__ __forceinline__ float bfhi(float x) {
    return __bfloat162float(__float2bfloat16(x));
}
__device__ __forceinline__ void cp_async16(u32 s, const void* g) {
    asm volatile("cp.async.cg.shared.global [%0], [%1], 16;" :: "r"(s), "l"(g));
}
#define CP_COMMIT() asm volatile("cp.async.commit_group;" ::: "memory")
#define CP_WAIT(n)  asm volatile("cp.async.wait_group %0;" :: "n"(n) : "memory")

// ---------------- scratch (static device globals) ------------------------------
__device__ float g_qT[N_SEQ * DIMC];                 // q[i][c]
__device__ float g_pos[GROUPS * M_SEQ];
__device__ __nv_bfloat16 g_khi[2 * M_SEQ * INNER];   // k hi  [s][t][c]
__device__ __nv_bfloat16 g_klo[2 * M_SEQ * INNER];   // k lo
__device__ __nv_bfloat16 g_vhi[2 * M_SEQ * INNER];   // v hi  [s][t][c]
__device__ __nv_bfloat16 g_vlo[2 * M_SEQ * INNER];   // v lo
__device__ float g_att[2 * N_SEQ * INNER];           // attn out [s][i][c]

#define SMSTRIDE 144
#define QSCL 0.1803368801111204f   // 0.125 * log2(e)
#define MSHIFT 24.0f               // fixed softmax shift (base-2); logits << 24

// ================= Kernel 1: q projection via warp-MMA =========================
#define OP_AHI 0
#define OP_ALO 9216
#define OP_BHI 18432
#define OP_BLO 27648

__global__ __launch_bounds__(128) void qproj_mma_kernel(
    const float* __restrict__ x, const float* __restrict__ px,
    const float* __restrict__ Wq)
{
    __shared__ __align__(16) char sm[36864];
    const int i0 = blockIdx.x * 64;
    const int g  = blockIdx.y;
    const int c0 = g * 64;
    const float* src = (g < 4) ? px : x;
    const int   base = (g & 3) * 128;
    const int tid = threadIdx.x;
    const int lane = tid & 31, wid = tid >> 5;
    const u32 smb = smem_u32(sm);

    float acc[8][4];
    #pragma unroll
    for (int nb = 0; nb < 8; nb++)
        #pragma unroll
        for (int u = 0; u < 4; u++) acc[nb][u] = 0.f;

    const u32 apos = (wid * 16 + (lane & 7) + ((lane >> 3) & 1) * 8) * SMSTRIDE
                   + ((lane >> 4) & 1) * 16;
    const u32 b4pos = (lane & 7) * SMSTRIDE + ((lane >> 3) & 1) * 16
                    + ((lane >> 4) & 1) * 9216;

    for (int k0 = 0; k0 < 128; k0 += 64) {
        __syncthreads();
        for (int idx = tid; idx < 2048; idx += 128) {
            int r = idx >> 5, c2 = idx & 31;
            float2 a = *(const float2*)&src[(size_t)(i0 + r) * DIMC + base + k0 + 2 * c2];
            float ah = bfhi(a.x), bh = bfhi(a.y);
            u32 so = r * SMSTRIDE + c2 * 4;
            *(u32*)(sm + OP_AHI + so) = pack_bf16(ah, bh);
            *(u32*)(sm + OP_ALO + so) = pack_bf16(a.x - ah, a.y - bh);
            float2 w = *(const float2*)&Wq[(c0 + r) * 128 + k0 + 2 * c2];
            float wh = bfhi(w.x), xh = bfhi(w.y);
            *(u32*)(sm + OP_BHI + so) = pack_bf16(wh, xh);
            *(u32*)(sm + OP_BLO + so) = pack_bf16(w.x - wh, w.y - xh);
        }
        __syncthreads();
        #pragma unroll
        for (int kb = 0; kb < 4; kb++) {
            u32 ah0, ah1, ah2, ah3, al0, al1, al2, al3;
            ldsm_x4(smb + OP_AHI + apos + kb * 32, ah0, ah1, ah2, ah3);
            ldsm_x4(smb + OP_ALO + apos + kb * 32, al0, al1, al2, al3);
            #pragma unroll
            for (int nb = 0; nb < 8; nb++) {
                u32 b0, b1, c0r, c1r;
                ldsm_x4(smb + OP_BHI + b4pos + nb * (8 * SMSTRIDE) + kb * 32, b0, b1, c0r, c1r);
                mma16816(acc[nb], ah0, ah1, ah2, ah3, b0, b1);
                mma16816(acc[nb], al0, al1, al2, al3, b0, b1);
                mma16816(acc[nb], ah0, ah1, ah2, ah3, c0r, c1r);
            }
        }
    }
    const int rA = wid * 16 + (lane >> 2), rB = rA + 8;
    #pragma unroll
    for (int nb = 0; nb < 8; nb++) {
        int col = nb * 8 + (lane & 3) * 2;
        *(float2*)&g_qT[(size_t)(i0 + rA) * DIMC + c0 + col] =
            make_float2(acc[nb][0], acc[nb][1]);
        *(float2*)&g_qT[(size_t)(i0 + rB) * DIMC + c0 + col] =
            make_float2(acc[nb][2], acc[nb][3]);
    }
}

// ================= Kernel 2: offset network ====================================
__global__ __launch_bounds__(128) void offset_kernel(
    const float* __restrict__ Wdw, const float* __restrict__ bdw,
    const float* __restrict__ Wp)
{
    const int g = blockIdx.y;
    const int t = blockIdx.x * 128 + threadIdx.x;
    const int pbase = 4 * t - 1;
    float s = 0.f;
    for (int c = 0; c < 64; c++) {
        float hv = bdw[c];
        #pragma unroll
        for (int k = 0; k < 6; k++) {
            int p = pbase + k;
            if (p >= 0 && p < N_SEQ) hv += Wdw[c * 6 + k] * g_qT[(size_t)p * DIMC + g * 64 + c];
        }
        hv = 0.5f * hv * (1.f + erff(hv * 0.7071067811865476f));
        s += Wp[c] * hv;
    }
    float off = tanhf(s) * 4.0f;
    float vg  = 2.0f * ((float)t + off) / 1023.0f - 1.0f;
    float pos = ((vg + 1.0f) * (float)N_SEQ - 1.0f) * 0.5f;
    g_pos[g * M_SEQ + t] = pos;
}

// ================= Kernel 3: fused gridsample + k/v projection =================
#define KV_AHI 0
#define KV_ALO 9216
#define KV_BHI 18432
#define KV_BLO 27648

__global__ __launch_bounds__(128) void kvproj_mma_kernel(
    const float* __restrict__ x, const float* __restrict__ px,
    const float* __restrict__ Wk, const float* __restrict__ Wv)
{
    __shared__ __align__(16) char sm[36864];
    const int t0 = blockIdx.x * 64;
    const int g  = blockIdx.y;
    const int s  = blockIdx.z & 1;
    const int which = blockIdx.z >> 1;
    const int c0 = g * 64;
    const float* W = which ? Wv : Wk;
    const float* src = (s == 0) ? px : x;
    __nv_bfloat16* ohi = which ? g_vhi : g_khi;
    __nv_bfloat16* olo = which ? g_vlo : g_klo;
    const int tid = threadIdx.x;
    const int lane = tid & 31, wid = tid >> 5;
    const u32 smb = smem_u32(sm);

    for (int idx = tid; idx < 2048; idx += 128) {
        int r = idx >> 5, c2 = idx & 31;
        const float pos = g_pos[g * M_SEQ + t0 + r];
        const float x0f = floorf(pos);
        const float w1 = pos - x0f;
        const int p0 = (int)x0f;
        const int ch = c0 + 2 * c2;
        float ax = 0.f, ay = 0.f;
        if (p0 >= 0 && p0 < N_SEQ) {
            float2 f = *(const float2*)&src[(size_t)p0 * DIMC + ch];
            ax += (1.f - w1) * f.x; ay += (1.f - w1) * f.y;
        }
        if (p0 + 1 >= 0 && p0 + 1 < N_SEQ) {
            float2 f = *(const float2*)&src[(size_t)(p0 + 1) * DIMC + ch];
            ax += w1 * f.x; ay += w1 * f.y;
        }
        float ah = bfhi(ax), bh = bfhi(ay);
        u32 so = r * SMSTRIDE + c2 * 4;
        *(u32*)(sm + KV_AHI + so) = pack_bf16(ah, bh);
        *(u32*)(sm + KV_ALO + so) = pack_bf16(ax - ah, ay - bh);
        float2 w = *(const float2*)&W[(c0 + r) * 64 + 2 * c2];
        float wh = bfhi(w.x), xh = bfhi(w.y);
        *(u32*)(sm + KV_BHI + so) = pack_bf16(wh, xh);
        *(u32*)(sm + KV_BLO + so) = pack_bf16(w.x - wh, w.y - xh);
    }
    __syncthreads();

    float acc[8][4];
    #pragma unroll
    for (int nb = 0; nb < 8; nb++)
        #pragma unroll
        for (int u = 0; u < 4; u++) acc[nb][u] = 0.f;

    const u32 apos = (wid * 16 + (lane & 7) + ((lane >> 3) & 1) * 8) * SMSTRIDE
                   + ((lane >> 4) & 1) * 16;
    const u32 b4pos = (lane & 7) * SMSTRIDE + ((lane >> 3) & 1) * 16
                    + ((lane >> 4) & 1) * 9216;

    #pragma unroll
    for (int kb = 0; kb < 4; kb++) {
        u32 ah0, ah1, ah2, ah3, al0, al1, al2, al3;
        ldsm_x4(smb + KV_AHI + apos + kb * 32, ah0, ah1, ah2, ah3);
        ldsm_x4(smb + KV_ALO + apos + kb * 32, al0, al1, al2, al3);
        #pragma unroll
        for (int nb = 0; nb < 8; nb++) {
            u32 b0, b1, c0r, c1r;
            ldsm_x4(smb + KV_BHI + b4pos + nb * (8 * SMSTRIDE) + kb * 32, b0, b1, c0r, c1r);
            mma16816(acc[nb], ah0, ah1, ah2, ah3, b0, b1);
            mma16816(acc[nb], al0, al1, al2, al3, b0, b1);
            mma16816(acc[nb], ah0, ah1, ah2, ah3, c0r, c1r);
        }
    }

    const int rA = wid * 16 + (lane >> 2), rB = rA + 8;
    #pragma unroll
    for (int nb = 0; nb < 8; nb++) {
        int col = nb * 8 + (lane & 3) * 2;
        float v0 = acc[nb][0], v1 = acc[nb][1];
        float v2 = acc[nb][2], v3 = acc[nb][3];
        float h0 = bfhi(v0), h1 = bfhi(v1), h2 = bfhi(v2), h3 = bfhi(v3);
        const int ch = c0 + col;
        const size_t iA = ((size_t)(s * M_SEQ + t0 + rA)) * INNER + ch;
        const size_t iB = ((size_t)(s * M_SEQ + t0 + rB)) * INNER + ch;
        *(u32*)&ohi[iA] = pack_bf16(h0, h1);
        *(u32*)&olo[iA] = pack_bf16(v0 - h0, v1 - h1);
        *(u32*)&ohi[iB] = pack_bf16(h2, h3);
        *(u32*)&olo[iB] = pack_bf16(v2 - h2, v3 - h3);
    }
}

// ================= Kernel 4: flash attention (fixed-shift softmax) =============
// Dynamic smem: QHI 0, QLO 18432, buf0 36864, buf1 73728 -> 110592 total
#define AQHI 0
#define AQLO 18432
#define ABASE 36864
#define AKHI 0
#define AKLO 9216
#define AVHI 18432
#define AVLO 27648
#define ABUF 36864

__global__ __launch_bounds__(256, 2) void attn_kernel()
{
    extern __shared__ __align__(16) char sm[];
    const int i0 = blockIdx.x * 128;
    const int h  = blockIdx.y;
    const int s  = blockIdx.z;
    const int tid = threadIdx.x;
    const int lane = tid & 31;
    const int wid = tid >> 5;
    const u32 smb = smem_u32(sm);

    // ---- stage Q (scaled, bf16 split) into persistent strip ----
    {
        const float* qbase = g_qT + (size_t)i0 * DIMC + h * 64;
        for (int idx = tid; idx < 4096; idx += 256) {
            int r = idx >> 5, c2 = idx & 31;
            const float* qp = qbase + (size_t)r * DIMC + 2 * c2;
            float a = qp[0] * QSCL, b = qp[1] * QSCL;
            float ah = bfhi(a), bh = bfhi(b);
            *(u32*)(sm + AQHI + r * SMSTRIDE + c2 * 4) = pack_bf16(ah, bh);
            *(u32*)(sm + AQLO + r * SMSTRIDE + c2 * 4) = pack_bf16(a - ah, b - bh);
        }
    }

    const __nv_bfloat16* khb = g_khi + (size_t)s * M_SEQ * INNER + h * 64;
    const __nv_bfloat16* klb = g_klo + (size_t)s * M_SEQ * INNER + h * 64;
    const __nv_bfloat16* vhb = g_vhi + (size_t)s * M_SEQ * INNER + h * 64;
    const __nv_bfloat16* vlb = g_vlo + (size_t)s * M_SEQ * INNER + h * 64;

    const u32 lpK = (lane & 7) * SMSTRIDE + ((lane >> 3) & 1) * 16;
    const u32 lpV = (lane & 7) * SMSTRIDE + ((lane >> 3) & 1) * (8 * SMSTRIDE);
    const u32 qfoff = smb + (wid * 16 + (lane & 7) + ((lane >> 3) & 1) * 8) * SMSTRIDE
                    + ((lane >> 4) & 1) * 16;

    float oacc[8][4];
    #pragma unroll
    for (int nd = 0; nd < 8; nd++)
        #pragma unroll
        for (int u = 0; u < 4; u++) oacc[nd][u] = 0.f;
    float lA = 0.f, lB = 0.f;     // thread-local partial denominators

    // prologue: issue tile 0 into buffer 0
    #pragma unroll
    for (int it = 0; it < 2; it++) {
        int slot = tid + it * 256;
        int r = slot >> 3, seg = slot & 7;
        size_t go = (size_t)r * INNER + seg * 8;
        u32 so = smb + ABASE + r * SMSTRIDE + seg * 16;
        cp_async16(so + AKHI, khb + go);
        cp_async16(so + AKLO, klb + go);
        cp_async16(so + AVHI, vhb + go);
        cp_async16(so + AVLO, vlb + go);
    }
    CP_COMMIT();

    for (int t = 0; t < 16; t++) {
        if (t + 1 < 16) {
            u32 bn = smb + ABASE + ((t + 1) & 1) * ABUF;
            #pragma unroll
            for (int it = 0; it < 2; it++) {
                int slot = tid + it * 256;
                int r = slot >> 3, seg = slot & 7;
                size_t go = (size_t)((t + 1) * 64 + r) * INNER + seg * 8;
                u32 so = bn + r * SMSTRIDE + seg * 16;
                cp_async16(so + AKHI, khb + go);
                cp_async16(so + AKLO, klb + go);
                cp_async16(so + AVHI, vhb + go);
                cp_async16(so + AVLO, vlb + go);
            }
            CP_COMMIT();
            CP_WAIT(1);
        } else {
            CP_WAIT(0);
        }
        __syncthreads();
        const u32 bb = smb + ABASE + (t & 1) * ABUF;

        // ---- S = Q K^T (hh + lh + hl), 64 keys; Q frags loaded per-kb ----
        float sacc[8][4];
        #pragma unroll
        for (int nb = 0; nb < 8; nb++)
            #pragma unroll
            for (int u = 0; u < 4; u++) sacc[nb][u] = 0.f;
        #pragma unroll
        for (int kb = 0; kb < 4; kb++) {
            u32 q0, q1, q2, q3, l0, l1, l2, l3;
            ldsm_x4(qfoff + AQHI + kb * 32, q0, q1, q2, q3);
            ldsm_x4(qfoff + AQLO + kb * 32, l0, l1, l2, l3);
            #pragma unroll
            for (int nb = 0; nb < 8; nb++) {
                u32 b0, b1, c0, c1;
                ldsm_x2(bb + AKHI + lpK + nb * (8 * SMSTRIDE) + kb * 32, b0, b1);
                mma16816(sacc[nb], q0, q1, q2, q3, b0, b1);
                mma16816(sacc[nb], l0, l1, l2, l3, b0, b1);
                ldsm_x2(bb + AKLO + lpK + nb * (8 * SMSTRIDE) + kb * 32, c0, c1);
                mma16816(sacc[nb], q0, q1, q2, q3, c0, c1);
            }
        }

        // ---- fixed-shift softmax: p = 2^(s - MSHIFT); no reductions, no rescale ----
        #pragma unroll
        for (int nb = 0; nb < 8; nb++) {
            sacc[nb][0] = ex2f(sacc[nb][0] - MSHIFT);
            sacc[nb][1] = ex2f(sacc[nb][1] - MSHIFT);
            sacc[nb][2] = ex2f(sacc[nb][2] - MSHIFT);
            sacc[nb][3] = ex2f(sacc[nb][3] - MSHIFT);
            lA += sacc[nb][0] + sacc[nb][1];
            lB += sacc[nb][2] + sacc[nb][3];
        }

        // ---- O += P V (ph*vh + pl*vh + ph*vl), 4 k-blocks of 16 keys ----
        #pragma unroll
        for (int kb = 0; kb < 4; kb++) {
            const float* pL = sacc[2 * kb];
            const float* pH = sacc[2 * kb + 1];
            float h00 = bfhi(pL[0]), h01 = bfhi(pL[1]), h02 = bfhi(pL[2]), h03 = bfhi(pL[3]);
            float h10 = bfhi(pH[0]), h11 = bfhi(pH[1]), h12 = bfhi(pH[2]), h13 = bfhi(pH[3]);
            u32 a0 = pack_bf16(h00, h01), a1 = pack_bf16(h02, h03);
            u32 a2 = pack_bf16(h10, h11), a3 = pack_bf16(h12, h13);
            u32 e0 = pack_bf16(pL[0] - h00, pL[1] - h01);
            u32 e1 = pack_bf16(pL[2] - h02, pL[3] - h03);
            u32 e2 = pack_bf16(pH[0] - h10, pH[1] - h11);
            u32 e3 = pack_bf16(pH[2] - h12, pH[3] - h13);
            #pragma unroll
            for (int nd = 0; nd < 8; nd++) {
                u32 b0, b1, c0, c1;
                ldsm_x2_t(bb + AVHI + lpV + kb * (16 * SMSTRIDE) + nd * 16, b0, b1);
                mma16816(oacc[nd], a0, a1, a2, a3, b0, b1);
                mma16816(oacc[nd], e0, e1, e2, e3, b0, b1);
                ldsm_x2_t(bb + AVLO + lpV + kb * (16 * SMSTRIDE) + nd * 16, c0, c1);
                mma16816(oacc[nd], a0, a1, a2, a3, c0, c1);
            }
        }
        __syncthreads();   // buffer consumed; safe for next issue
    }

    // ---- epilogue: reduce l across the 4 lanes of each row, normalize, store ----
    lA += __shfl_xor_sync(0xffffffffu, lA, 1);
    lA += __shfl_xor_sync(0xffffffffu, lA, 2);
    lB += __shfl_xor_sync(0xffffffffu, lB, 1);
    lB += __shfl_xor_sync(0xffffffffu, lB, 2);
    float invA = 1.f / lA, invB = 1.f / lB;
    const int rA = wid * 16 + (lane >> 2), rB = rA + 8;
    float* oA = g_att + (size_t)s * N_SEQ * INNER + (size_t)(i0 + rA) * INNER + h * 64;
    float* oB = g_att + (size_t)s * N_SEQ * INNER + (size_t)(i0 + rB) * INNER + h * 64;
    #pragma unroll
    for (int nd = 0; nd < 8; nd++) {
        int col = nd * 8 + (lane & 3) * 2;
        *(float2*)&oA[col] = make_float2(oacc[nd][0] * invA, oacc[nd][1] * invA);
        *(float2*)&oB[col] = make_float2(oacc[nd][2] * invB, oacc[nd][3] * invB);
    }
}

// ================= Kernel 5: stream-mean + Wo GEMM (warp-MMA) ==================
__global__ __launch_bounds__(128) void outproj_mma_kernel(
    const float* __restrict__ Wo, const float* __restrict__ bo,
    float* __restrict__ out)
{
    __shared__ __align__(16) char sm[36864];
    const int i0 = blockIdx.x * 64;
    const int d0 = blockIdx.y * 64;
    const int tid = threadIdx.x;
    const int lane = tid & 31, wid = tid >> 5;
    const u32 smb = smem_u32(sm);

    float acc[8][4];
    #pragma unroll
    for (int nb = 0; nb < 8; nb++)
        #pragma unroll
        for (int u = 0; u < 4; u++) acc[nb][u] = 0.f;

    const u32 apos = (wid * 16 + (lane & 7) + ((lane >> 3) & 1) * 8) * SMSTRIDE
                   + ((lane >> 4) & 1) * 16;
    const u32 b4pos = (lane & 7) * SMSTRIDE + ((lane >> 3) & 1) * 16
                    + ((lane >> 4) & 1) * 9216;

    for (int k0 = 0; k0 < 512; k0 += 64) {
        __syncthreads();
        for (int idx = tid; idx < 2048; idx += 128) {
            int r = idx >> 5, c2 = idx & 31;
            const float* a0p = &g_att[(size_t)(i0 + r) * INNER + k0 + 2 * c2];
            float2 u0 = *(const float2*)a0p;
            float2 u1 = *(const float2*)(a0p + (size_t)N_SEQ * INNER);
            float ax = 0.5f * (u0.x + u1.x), ay = 0.5f * (u0.y + u1.y);
            float ah = bfhi(ax), bh = bfhi(ay);
            u32 so = r * SMSTRIDE + c2 * 4;
            *(u32*)(sm + OP_AHI + so) = pack_bf16(ah, bh);
            *(u32*)(sm + OP_ALO + so) = pack_bf16(ax - ah, ay - bh);
            float2 w = *(const float2*)&Wo[(d0 + r) * INNER + k0 + 2 * c2];
            float wh = bfhi(w.x), xh = bfhi(w.y);
            *(u32*)(sm + OP_BHI + so) = pack_bf16(wh, xh);
            *(u32*)(sm + OP_BLO + so) = pack_bf16(w.x - wh, w.y - xh);
        }
        __syncthreads();

        #pragma unroll
        for (int kb = 0; kb < 4; kb++) {
            u32 ah0, ah1, ah2, ah3, al0, al1, al2, al3;
            ldsm_x4(smb + OP_AHI + apos + kb * 32, ah0, ah1, ah2, ah3);
            ldsm_x4(smb + OP_ALO + apos + kb * 32, al0, al1, al2, al3);
            #pragma unroll
            for (int nb = 0; nb < 8; nb++) {
                u32 b0, b1, c0r, c1r;
                ldsm_x4(smb + OP_BHI + b4pos + nb * (8 * SMSTRIDE) + kb * 32, b0, b1, c0r, c1r);
                mma16816(acc[nb], ah0, ah1, ah2, ah3, b0, b1);
                mma16816(acc[nb], al0, al1, al2, al3, b0, b1);
                mma16816(acc[nb], ah0, ah1, ah2, ah3, c0r, c1r);
            }
        }
    }

    const int rA = wid * 16 + (lane >> 2), rB = rA + 8;
    #pragma unroll
    for (int nb = 0; nb < 8; nb++) {
        int col = nb * 8 + (lane & 3) * 2;
        float b0 = bo[d0 + col], b1 = bo[d0 + col + 1];
        *(float2*)&out[(size_t)(i0 + rA) * DIMC + d0 + col] =
            make_float2(acc[nb][0] + b0, acc[nb][1] + b1);
        *(float2*)&out[(size_t)(i0 + rB) * DIMC + d0 + col] =
            make_float2(acc[nb][2] + b0, acc[nb][3] + b1);
    }
}

// ================= launch ======================================================
extern "C" void kernel_launch(void* const* d_in, const int* in_sizes, int n_in,
                              void* d_out, int out_size)
{
    const float* x   = (const float*)d_in[0];
    const float* px  = (const float*)d_in[1];
    const float* Wq  = (const float*)d_in[2];
    const float* Wk  = (const float*)d_in[3];
    const float* Wv  = (const float*)d_in[4];
    const float* Wo  = (const float*)d_in[5];
    const float* bo  = (const float*)d_in[6];
    const float* Wdw = (const float*)d_in[7];
    const float* bdw = (const float*)d_in[8];
    const float* Wp  = (const float*)d_in[9];
    float* out = (float*)d_out;

    cudaFuncSetAttribute(attn_kernel,
                         cudaFuncAttributeMaxDynamicSharedMemorySize, ABASE + 2 * ABUF);

    qproj_mma_kernel<<<dim3(64, 8), 128>>>(x, px, Wq);
    offset_kernel<<<dim3(8, 8), 128>>>(Wdw, bdw, Wp);
    kvproj_mma_kernel<<<dim3(16, 8, 4), 128>>>(x, px, Wk, Wv);
    attn_kernel<<<dim3(32, HEADS, 2), 256, ABASE + 2 * ABUF>>>();
    outproj_mma_kernel<<<dim3(64, 8), 128>>>(Wo, bo, out);
}

// round 17
// speedup vs baseline: 1.4794x; 1.4794x over previous
#include <cuda_runtime.h>
#include <cuda_bf16.h>
#include <math.h>

typedef unsigned int u32;
typedef unsigned short u16;
typedef unsigned char u8;
typedef unsigned long long u64;
typedef unsigned long long ull;

#define N_SEQ 4096
#define M_SEQ 1024
#define DIMC  512
#define INNER 512
#define HEADS 8
#define GROUPS 8

// ---------------- warp-MMA helpers -------------------------------------------
__device__ __forceinline__ u32 smem_u32(const void* p) {
    u32 a;
    asm("{ .reg .u64 t; cvta.to.shared.u64 t, %1; cvt.u32.u64 %0, t; }" : "=r"(a) : "l"(p));
    return a;
}
__device__ __forceinline__ float ex2f(float x) {
    float r; asm("ex2.approx.ftz.f32 %0, %1;" : "=f"(r) : "f"(x)); return r;
}
__device__ __forceinline__ void ldsm_x4(u32 addr, u32& r0, u32& r1, u32& r2, u32& r3) {
    asm volatile("ldmatrix.sync.aligned.m8n8.x4.shared.b16 {%0,%1,%2,%3}, [%4];"
        : "=r"(r0), "=r"(r1), "=r"(r2), "=r"(r3) : "r"(addr));
}
__device__ __forceinline__ void ldsm_x2(u32 addr, u32& r0, u32& r1) {
    asm volatile("ldmatrix.sync.aligned.m8n8.x2.shared.b16 {%0,%1}, [%2];"
        : "=r"(r0), "=r"(r1) : "r"(addr));
}
__device__ __forceinline__ void ldsm_x2_t(u32 addr, u32& r0, u32& r1) {
    asm volatile("ldmatrix.sync.aligned.m8n8.x2.trans.shared.b16 {%0,%1}, [%2];"
        : "=r"(r0), "=r"(r1) : "r"(addr));
}
__device__ __forceinline__ void mma16816(float* c, u32 a0, u32 a1, u32 a2, u32 a3,
                                         u32 b0, u32 b1) {
    asm volatile(
        "mma.sync.aligned.m16n8k16.row.col.f32.bf16.bf16.f32 "
        "{%0,%1,%2,%3}, {%4,%5,%6,%7}, {%8,%9}, {%0,%1,%2,%3};"
        : "+f"(c[0]), "+f"(c[1]), "+f"(c[2]), "+f"(c[3])
        : "r"(a0), "r"(a1), "r"(a2), "r"(a3), "r"(b0), "r"(b1));
}
__device__ __forceinline__ u32 pack_bf16(float a, float b) {
    return ((u32)__bfloat16_as_ushort(__float2bfloat16(b)) << 16) |
           (u32)__bfloat16_as_ushort(__float2bfloat16(a));
}
__device__ __forceinline__ float bfhi(float x) {
    return __bfloat162float(__float2bfloat16(x));
}
__device__ __forceinline__ void cp_async16(u32 s, const void* g) {
    asm volatile("cp.async.cg.shared.global [%0], [%1], 16;" :: "r"(s), "l"(g));
}
#define CP_COMMIT() asm volatile("cp.async.commit_group;" ::: "memory")
#define CP_WAIT(n)  asm volatile("cp.async.wait_group %0;" :: "n"(n) : "memory")

// ---------------- scratch (static device globals) ------------------------------
__device__ float g_qT[N_SEQ * DIMC];                 // q[i][c]
__device__ float g_pos[GROUPS * M_SEQ];
__device__ __nv_bfloat16 g_khi[2 * M_SEQ * INNER];   // k hi  [s][t][c]
__device__ __nv_bfloat16 g_klo[2 * M_SEQ * INNER];   // k lo
__device__ __nv_bfloat16 g_vhi[2 * M_SEQ * INNER];   // v hi  [s][t][c]
__device__ __nv_bfloat16 g_vlo[2 * M_SEQ * INNER];   // v lo
__device__ float g_att[2 * N_SEQ * INNER];           // attn out [s][i][c]

#define SMSTRIDE 144
#define QSCL 0.1803368801111204f   // 0.125 * log2(e)

// 128-row GEMM smem layout (dynamic, 55296 B)
#define GP_AHI 0
#define GP_ALO 18432
#define GP_BHI 36864
#define GP_BLO 46080
#define GP_TOTAL 55296

// ================= Kernel 1: q projection (256 thr, 128-row tiles) =============
__global__ __launch_bounds__(256, 2) void qproj_mma_kernel(
    const float* __restrict__ x, const float* __restrict__ px,
    const float* __restrict__ Wq)
{
    extern __shared__ __align__(16) char sm[];
    const int i0 = blockIdx.x * 128;
    const int g  = blockIdx.y;
    const int c0 = g * 64;
    const float* src = (g < 4) ? px : x;
    const int   base = (g & 3) * 128;
    const int tid = threadIdx.x;
    const int lane = tid & 31, wid = tid >> 5;
    const u32 smb = smem_u32(sm);

    float acc[8][4];
    #pragma unroll
    for (int nb = 0; nb < 8; nb++)
        #pragma unroll
        for (int u = 0; u < 4; u++) acc[nb][u] = 0.f;

    const u32 apos = (wid * 16 + (lane & 7) + ((lane >> 3) & 1) * 8) * SMSTRIDE
                   + ((lane >> 4) & 1) * 16;
    const u32 bpos = (lane & 7) * SMSTRIDE + ((lane >> 3) & 1) * 16;

    for (int k0 = 0; k0 < 128; k0 += 64) {
        __syncthreads();
        for (int idx = tid; idx < 4096; idx += 256) {      // A: 128 rows
            int r = idx >> 5, c2 = idx & 31;
            float2 a = *(const float2*)&src[(size_t)(i0 + r) * DIMC + base + k0 + 2 * c2];
            float ah = bfhi(a.x), bh = bfhi(a.y);
            u32 so = r * SMSTRIDE + c2 * 4;
            *(u32*)(sm + GP_AHI + so) = pack_bf16(ah, bh);
            *(u32*)(sm + GP_ALO + so) = pack_bf16(a.x - ah, a.y - bh);
        }
        for (int idx = tid; idx < 2048; idx += 256) {      // B: 64 rows
            int r = idx >> 5, c2 = idx & 31;
            float2 w = *(const float2*)&Wq[(c0 + r) * 128 + k0 + 2 * c2];
            float wh = bfhi(w.x), xh = bfhi(w.y);
            u32 so = r * SMSTRIDE + c2 * 4;
            *(u32*)(sm + GP_BHI + so) = pack_bf16(wh, xh);
            *(u32*)(sm + GP_BLO + so) = pack_bf16(w.x - wh, w.y - xh);
        }
        __syncthreads();
        #pragma unroll
        for (int kb = 0; kb < 4; kb++) {
            u32 ah0, ah1, ah2, ah3, al0, al1, al2, al3;
            ldsm_x4(smb + GP_AHI + apos + kb * 32, ah0, ah1, ah2, ah3);
            ldsm_x4(smb + GP_ALO + apos + kb * 32, al0, al1, al2, al3);
            #pragma unroll
            for (int nb = 0; nb < 8; nb++) {
                u32 b0, b1, c0r, c1r;
                ldsm_x2(smb + GP_BHI + bpos + nb * (8 * SMSTRIDE) + kb * 32, b0, b1);
                mma16816(acc[nb], ah0, ah1, ah2, ah3, b0, b1);
                mma16816(acc[nb], al0, al1, al2, al3, b0, b1);
                ldsm_x2(smb + GP_BLO + bpos + nb * (8 * SMSTRIDE) + kb * 32, c0r, c1r);
                mma16816(acc[nb], ah0, ah1, ah2, ah3, c0r, c1r);
            }
        }
    }
    const int rA = wid * 16 + (lane >> 2), rB = rA + 8;
    #pragma unroll
    for (int nb = 0; nb < 8; nb++) {
        int col = nb * 8 + (lane & 3) * 2;
        *(float2*)&g_qT[(size_t)(i0 + rA) * DIMC + c0 + col] =
            make_float2(acc[nb][0], acc[nb][1]);
        *(float2*)&g_qT[(size_t)(i0 + rB) * DIMC + c0 + col] =
            make_float2(acc[nb][2], acc[nb][3]);
    }
}

// ================= Kernel 2: offset network ====================================
__global__ __launch_bounds__(128) void offset_kernel(
    const float* __restrict__ Wdw, const float* __restrict__ bdw,
    const float* __restrict__ Wp)
{
    const int g = blockIdx.y;
    const int t = blockIdx.x * 128 + threadIdx.x;
    const int pbase = 4 * t - 1;
    float s = 0.f;
    for (int c = 0; c < 64; c++) {
        float hv = bdw[c];
        #pragma unroll
        for (int k = 0; k < 6; k++) {
            int p = pbase + k;
            if (p >= 0 && p < N_SEQ) hv += Wdw[c * 6 + k] * g_qT[(size_t)p * DIMC + g * 64 + c];
        }
        hv = 0.5f * hv * (1.f + erff(hv * 0.7071067811865476f));
        s += Wp[c] * hv;
    }
    float off = tanhf(s) * 4.0f;
    float vg  = 2.0f * ((float)t + off) / 1023.0f - 1.0f;
    float pos = ((vg + 1.0f) * (float)N_SEQ - 1.0f) * 0.5f;
    g_pos[g * M_SEQ + t] = pos;
}

// ================= Kernel 3: fused gridsample + k/v projection =================
#define KV_AHI 0
#define KV_ALO 9216
#define KV_BHI 18432
#define KV_BLO 27648

__global__ __launch_bounds__(128) void kvproj_mma_kernel(
    const float* __restrict__ x, const float* __restrict__ px,
    const float* __restrict__ Wk, const float* __restrict__ Wv)
{
    __shared__ __align__(16) char sm[36864];
    const int t0 = blockIdx.x * 64;
    const int g  = blockIdx.y;
    const int s  = blockIdx.z & 1;
    const int which = blockIdx.z >> 1;
    const int c0 = g * 64;
    const float* W = which ? Wv : Wk;
    const float* src = (s == 0) ? px : x;
    __nv_bfloat16* ohi = which ? g_vhi : g_khi;
    __nv_bfloat16* olo = which ? g_vlo : g_klo;
    const int tid = threadIdx.x;
    const int lane = tid & 31, wid = tid >> 5;
    const u32 smb = smem_u32(sm);

    for (int idx = tid; idx < 2048; idx += 128) {
        int r = idx >> 5, c2 = idx & 31;
        const float pos = g_pos[g * M_SEQ + t0 + r];
        const float x0f = floorf(pos);
        const float w1 = pos - x0f;
        const int p0 = (int)x0f;
        const int ch = c0 + 2 * c2;
        float ax = 0.f, ay = 0.f;
        if (p0 >= 0 && p0 < N_SEQ) {
            float2 f = *(const float2*)&src[(size_t)p0 * DIMC + ch];
            ax += (1.f - w1) * f.x; ay += (1.f - w1) * f.y;
        }
        if (p0 + 1 >= 0 && p0 + 1 < N_SEQ) {
            float2 f = *(const float2*)&src[(size_t)(p0 + 1) * DIMC + ch];
            ax += w1 * f.x; ay += w1 * f.y;
        }
        float ah = bfhi(ax), bh = bfhi(ay);
        u32 so = r * SMSTRIDE + c2 * 4;
        *(u32*)(sm + KV_AHI + so) = pack_bf16(ah, bh);
        *(u32*)(sm + KV_ALO + so) = pack_bf16(ax - ah, ay - bh);
        float2 w = *(const float2*)&W[(c0 + r) * 64 + 2 * c2];
        float wh = bfhi(w.x), xh = bfhi(w.y);
        *(u32*)(sm + KV_BHI + so) = pack_bf16(wh, xh);
        *(u32*)(sm + KV_BLO + so) = pack_bf16(w.x - wh, w.y - xh);
    }
    __syncthreads();

    float acc[8][4];
    #pragma unroll
    for (int nb = 0; nb < 8; nb++)
        #pragma unroll
        for (int u = 0; u < 4; u++) acc[nb][u] = 0.f;

    const u32 apos = (wid * 16 + (lane & 7) + ((lane >> 3) & 1) * 8) * SMSTRIDE
                   + ((lane >> 4) & 1) * 16;
    const u32 bpos = (lane & 7) * SMSTRIDE + ((lane >> 3) & 1) * 16;

    #pragma unroll
    for (int kb = 0; kb < 4; kb++) {
        u32 ah0, ah1, ah2, ah3, al0, al1, al2, al3;
        ldsm_x4(smb + KV_AHI + apos + kb * 32, ah0, ah1, ah2, ah3);
        ldsm_x4(smb + KV_ALO + apos + kb * 32, al0, al1, al2, al3);
        #pragma unroll
        for (int nb = 0; nb < 8; nb++) {
            u32 b0, b1, c0r, c1r;
            ldsm_x2(smb + KV_BHI + bpos + nb * (8 * SMSTRIDE) + kb * 32, b0, b1);
            mma16816(acc[nb], ah0, ah1, ah2, ah3, b0, b1);
            mma16816(acc[nb], al0, al1, al2, al3, b0, b1);
            ldsm_x2(smb + KV_BLO + bpos + nb * (8 * SMSTRIDE) + kb * 32, c0r, c1r);
            mma16816(acc[nb], ah0, ah1, ah2, ah3, c0r, c1r);
        }
    }

    const int rA = wid * 16 + (lane >> 2), rB = rA + 8;
    #pragma unroll
    for (int nb = 0; nb < 8; nb++) {
        int col = nb * 8 + (lane & 3) * 2;
        float v0 = acc[nb][0], v1 = acc[nb][1];
        float v2 = acc[nb][2], v3 = acc[nb][3];
        float h0 = bfhi(v0), h1 = bfhi(v1), h2 = bfhi(v2), h3 = bfhi(v3);
        const int ch = c0 + col;
        const size_t iA = ((size_t)(s * M_SEQ + t0 + rA)) * INNER + ch;
        const size_t iB = ((size_t)(s * M_SEQ + t0 + rB)) * INNER + ch;
        *(u32*)&ohi[iA] = pack_bf16(h0, h1);
        *(u32*)&olo[iA] = pack_bf16(v0 - h0, v1 - h1);
        *(u32*)&ohi[iB] = pack_bf16(h2, h3);
        *(u32*)&olo[iB] = pack_bf16(v2 - h2, v3 - h3);
    }
}

// ================= Kernel 4: flash attention (R12 verbatim) ====================
// Dynamic smem: QHI 0, QLO 18432, buf0 36864, buf1 73728 -> 110592 total
#define AQHI 0
#define AQLO 18432
#define ABASE 36864
#define AKHI 0
#define AKLO 9216
#define AVHI 18432
#define AVLO 27648
#define ABUF 36864

__global__ __launch_bounds__(256, 2) void attn_kernel()
{
    extern __shared__ __align__(16) char sm[];
    const int i0 = blockIdx.x * 128;
    const int h  = blockIdx.y;
    const int s  = blockIdx.z;
    const int tid = threadIdx.x;
    const int lane = tid & 31;
    const int wid = tid >> 5;
    const u32 smb = smem_u32(sm);

    // ---- stage Q (scaled, bf16 split) into persistent strip ----
    {
        const float* qbase = g_qT + (size_t)i0 * DIMC + h * 64;
        for (int idx = tid; idx < 4096; idx += 256) {
            int r = idx >> 5, c2 = idx & 31;
            const float* qp = qbase + (size_t)r * DIMC + 2 * c2;
            float a = qp[0] * QSCL, b = qp[1] * QSCL;
            float ah = bfhi(a), bh = bfhi(b);
            *(u32*)(sm + AQHI + r * SMSTRIDE + c2 * 4) = pack_bf16(ah, bh);
            *(u32*)(sm + AQLO + r * SMSTRIDE + c2 * 4) = pack_bf16(a - ah, b - bh);
        }
    }

    const __nv_bfloat16* khb = g_khi + (size_t)s * M_SEQ * INNER + h * 64;
    const __nv_bfloat16* klb = g_klo + (size_t)s * M_SEQ * INNER + h * 64;
    const __nv_bfloat16* vhb = g_vhi + (size_t)s * M_SEQ * INNER + h * 64;
    const __nv_bfloat16* vlb = g_vlo + (size_t)s * M_SEQ * INNER + h * 64;

    const u32 lpK = (lane & 7) * SMSTRIDE + ((lane >> 3) & 1) * 16;
    const u32 lpV = (lane & 7) * SMSTRIDE + ((lane >> 3) & 1) * (8 * SMSTRIDE);
    const u32 qfoff = smb + (wid * 16 + (lane & 7) + ((lane >> 3) & 1) * 8) * SMSTRIDE
                    + ((lane >> 4) & 1) * 16;

    float oacc[8][4];
    #pragma unroll
    for (int nd = 0; nd < 8; nd++)
        #pragma unroll
        for (int u = 0; u < 4; u++) oacc[nd][u] = 0.f;
    float mA = -1e30f, mB = -1e30f, lA = 0.f, lB = 0.f;

    // prologue: issue tile 0 into buffer 0
    #pragma unroll
    for (int it = 0; it < 2; it++) {
        int slot = tid + it * 256;
        int r = slot >> 3, seg = slot & 7;
        size_t go = (size_t)r * INNER + seg * 8;
        u32 so = smb + ABASE + r * SMSTRIDE + seg * 16;
        cp_async16(so + AKHI, khb + go);
        cp_async16(so + AKLO, klb + go);
        cp_async16(so + AVHI, vhb + go);
        cp_async16(so + AVLO, vlb + go);
    }
    CP_COMMIT();

    for (int t = 0; t < 16; t++) {
        if (t + 1 < 16) {
            u32 bn = smb + ABASE + ((t + 1) & 1) * ABUF;
            #pragma unroll
            for (int it = 0; it < 2; it++) {
                int slot = tid + it * 256;
                int r = slot >> 3, seg = slot & 7;
                size_t go = (size_t)((t + 1) * 64 + r) * INNER + seg * 8;
                u32 so = bn + r * SMSTRIDE + seg * 16;
                cp_async16(so + AKHI, khb + go);
                cp_async16(so + AKLO, klb + go);
                cp_async16(so + AVHI, vhb + go);
                cp_async16(so + AVLO, vlb + go);
            }
            CP_COMMIT();
            CP_WAIT(1);
        } else {
            CP_WAIT(0);
        }
        __syncthreads();
        const u32 bb = smb + ABASE + (t & 1) * ABUF;

        // ---- S = Q K^T (hh + lh + hl), 64 keys; Q frags loaded per-kb ----
        float sacc[8][4];
        #pragma unroll
        for (int nb = 0; nb < 8; nb++)
            #pragma unroll
            for (int u = 0; u < 4; u++) sacc[nb][u] = 0.f;
        #pragma unroll
        for (int kb = 0; kb < 4; kb++) {
            u32 q0, q1, q2, q3, l0, l1, l2, l3;
            ldsm_x4(qfoff + AQHI + kb * 32, q0, q1, q2, q3);
            ldsm_x4(qfoff + AQLO + kb * 32, l0, l1, l2, l3);
            #pragma unroll
            for (int nb = 0; nb < 8; nb++) {
                u32 b0, b1, c0, c1;
                ldsm_x2(bb + AKHI + lpK + nb * (8 * SMSTRIDE) + kb * 32, b0, b1);
                mma16816(sacc[nb], q0, q1, q2, q3, b0, b1);
                mma16816(sacc[nb], l0, l1, l2, l3, b0, b1);
                ldsm_x2(bb + AKLO + lpK + nb * (8 * SMSTRIDE) + kb * 32, c0, c1);
                mma16816(sacc[nb], q0, q1, q2, q3, c0, c1);
            }
        }

        // ---- online softmax (base-2) ----
        float tA = -1e30f, tB = -1e30f;
        #pragma unroll
        for (int nb = 0; nb < 8; nb++) {
            tA = fmaxf(tA, fmaxf(sacc[nb][0], sacc[nb][1]));
            tB = fmaxf(tB, fmaxf(sacc[nb][2], sacc[nb][3]));
        }
        tA = fmaxf(tA, __shfl_xor_sync(0xffffffffu, tA, 1));
        tA = fmaxf(tA, __shfl_xor_sync(0xffffffffu, tA, 2));
        tB = fmaxf(tB, __shfl_xor_sync(0xffffffffu, tB, 1));
        tB = fmaxf(tB, __shfl_xor_sync(0xffffffffu, tB, 2));
        float mAn = fmaxf(mA, tA), mBn = fmaxf(mB, tB);
        float cA = ex2f(mA - mAn), cB = ex2f(mB - mBn);
        mA = mAn; mB = mBn;
        float sA = 0.f, sB = 0.f;
        #pragma unroll
        for (int nb = 0; nb < 8; nb++) {
            sacc[nb][0] = ex2f(sacc[nb][0] - mAn);
            sacc[nb][1] = ex2f(sacc[nb][1] - mAn);
            sacc[nb][2] = ex2f(sacc[nb][2] - mBn);
            sacc[nb][3] = ex2f(sacc[nb][3] - mBn);
            sA += sacc[nb][0] + sacc[nb][1];
            sB += sacc[nb][2] + sacc[nb][3];
        }
        sA += __shfl_xor_sync(0xffffffffu, sA, 1);
        sA += __shfl_xor_sync(0xffffffffu, sA, 2);
        sB += __shfl_xor_sync(0xffffffffu, sB, 1);
        sB += __shfl_xor_sync(0xffffffffu, sB, 2);
        lA = lA * cA + sA;
        lB = lB * cB + sB;
        #pragma unroll
        for (int nd = 0; nd < 8; nd++) {
            oacc[nd][0] *= cA; oacc[nd][1] *= cA;
            oacc[nd][2] *= cB; oacc[nd][3] *= cB;
        }

        // ---- O += P V (ph*vh + pl*vh + ph*vl), 4 k-blocks of 16 keys ----
        #pragma unroll
        for (int kb = 0; kb < 4; kb++) {
            const float* pL = sacc[2 * kb];
            const float* pH = sacc[2 * kb + 1];
            float h00 = bfhi(pL[0]), h01 = bfhi(pL[1]), h02 = bfhi(pL[2]), h03 = bfhi(pL[3]);
            float h10 = bfhi(pH[0]), h11 = bfhi(pH[1]), h12 = bfhi(pH[2]), h13 = bfhi(pH[3]);
            u32 a0 = pack_bf16(h00, h01), a1 = pack_bf16(h02, h03);
            u32 a2 = pack_bf16(h10, h11), a3 = pack_bf16(h12, h13);
            u32 e0 = pack_bf16(pL[0] - h00, pL[1] - h01);
            u32 e1 = pack_bf16(pL[2] - h02, pL[3] - h03);
            u32 e2 = pack_bf16(pH[0] - h10, pH[1] - h11);
            u32 e3 = pack_bf16(pH[2] - h12, pH[3] - h13);
            #pragma unroll
            for (int nd = 0; nd < 8; nd++) {
                u32 b0, b1, c0, c1;
                ldsm_x2_t(bb + AVHI + lpV + kb * (16 * SMSTRIDE) + nd * 16, b0, b1);
                mma16816(oacc[nd], a0, a1, a2, a3, b0, b1);
                mma16816(oacc[nd], e0, e1, e2, e3, b0, b1);
                ldsm_x2_t(bb + AVLO + lpV + kb * (16 * SMSTRIDE) + nd * 16, c0, c1);
                mma16816(oacc[nd], a0, a1, a2, a3, c0, c1);
            }
        }
        __syncthreads();   // buffer consumed; safe for next issue
    }

    // ---- epilogue: normalize, store to g_att[s][i][c] ----
    float invA = 1.f / lA, invB = 1.f / lB;
    const int rA = wid * 16 + (lane >> 2), rB = rA + 8;
    float* oA = g_att + (size_t)s * N_SEQ * INNER + (size_t)(i0 + rA) * INNER + h * 64;
    float* oB = g_att + (size_t)s * N_SEQ * INNER + (size_t)(i0 + rB) * INNER + h * 64;
    #pragma unroll
    for (int nd = 0; nd < 8; nd++) {
        int col = nd * 8 + (lane & 3) * 2;
        *(float2*)&oA[col] = make_float2(oacc[nd][0] * invA, oacc[nd][1] * invA);
        *(float2*)&oB[col] = make_float2(oacc[nd][2] * invB, oacc[nd][3] * invB);
    }
}

// ================= Kernel 5: stream-mean + Wo GEMM (256 thr, 128 rows) =========
__global__ __launch_bounds__(256, 2) void outproj_mma_kernel(
    const float* __restrict__ Wo, const float* __restrict__ bo,
    float* __restrict__ out)
{
    extern __shared__ __align__(16) char sm[];
    const int i0 = blockIdx.x * 128;
    const int d0 = blockIdx.y * 64;
    const int tid = threadIdx.x;
    const int lane = tid & 31, wid = tid >> 5;
    const u32 smb = smem_u32(sm);

    float acc[8][4];
    #pragma unroll
    for (int nb = 0; nb < 8; nb++)
        #pragma unroll
        for (int u = 0; u < 4; u++) acc[nb][u] = 0.f;

    const u32 apos = (wid * 16 + (lane & 7) + ((lane >> 3) & 1) * 8) * SMSTRIDE
                   + ((lane >> 4) & 1) * 16;
    const u32 bpos = (lane & 7) * SMSTRIDE + ((lane >> 3) & 1) * 16;

    for (int k0 = 0; k0 < 512; k0 += 64) {
        __syncthreads();
        for (int idx = tid; idx < 4096; idx += 256) {      // A: 128 rows (mean)
            int r = idx >> 5, c2 = idx & 31;
            const float* a0p = &g_att[(size_t)(i0 + r) * INNER + k0 + 2 * c2];
            float2 u0 = *(const float2*)a0p;
            float2 u1 = *(const float2*)(a0p + (size_t)N_SEQ * INNER);
            float ax = 0.5f * (u0.x + u1.x), ay = 0.5f * (u0.y + u1.y);
            float ah = bfhi(ax), bh = bfhi(ay);
            u32 so = r * SMSTRIDE + c2 * 4;
            *(u32*)(sm + GP_AHI + so) = pack_bf16(ah, bh);
            *(u32*)(sm + GP_ALO + so) = pack_bf16(ax - ah, ay - bh);
        }
        for (int idx = tid; idx < 2048; idx += 256) {      // B: 64 rows (Wo)
            int r = idx >> 5, c2 = idx & 31;
            float2 w = *(const float2*)&Wo[(d0 + r) * INNER + k0 + 2 * c2];
            float wh = bfhi(w.x), xh = bfhi(w.y);
            u32 so = r * SMSTRIDE + c2 * 4;
            *(u32*)(sm + GP_BHI + so) = pack_bf16(wh, xh);
            *(u32*)(sm + GP_BLO + so) = pack_bf16(w.x - wh, w.y - xh);
        }
        __syncthreads();

        #pragma unroll
        for (int kb = 0; kb < 4; kb++) {
            u32 ah0, ah1, ah2, ah3, al0, al1, al2, al3;
            ldsm_x4(smb + GP_AHI + apos + kb * 32, ah0, ah1, ah2, ah3);
            ldsm_x4(smb + GP_ALO + apos + kb * 32, al0, al1, al2, al3);
            #pragma unroll
            for (int nb = 0; nb < 8; nb++) {
                u32 b0, b1, c0r, c1r;
                ldsm_x2(smb + GP_BHI + bpos + nb * (8 * SMSTRIDE) + kb * 32, b0, b1);
                mma16816(acc[nb], ah0, ah1, ah2, ah3, b0, b1);
                mma16816(acc[nb], al0, al1, al2, al3, b0, b1);
                ldsm_x2(smb + GP_BLO + bpos + nb * (8 * SMSTRIDE) + kb * 32, c0r, c1r);
                mma16816(acc[nb], ah0, ah1, ah2, ah3, c0r, c1r);
            }
        }
    }

    const int rA = wid * 16 + (lane >> 2), rB = rA + 8;
    #pragma unroll
    for (int nb = 0; nb < 8; nb++) {
        int col = nb * 8 + (lane & 3) * 2;
        float b0 = bo[d0 + col], b1 = bo[d0 + col + 1];
        *(float2*)&out[(size_t)(i0 + rA) * DIMC + d0 + col] =
            make_float2(acc[nb][0] + b0, acc[nb][1] + b1);
        *(float2*)&out[(size_t)(i0 + rB) * DIMC + d0 + col] =
            make_float2(acc[nb][2] + b0, acc[nb][3] + b1);
    }
}

// ================= launch ======================================================
extern "C" void kernel_launch(void* const* d_in, const int* in_sizes, int n_in,
                              void* d_out, int out_size)
{
    const float* x   = (const float*)d_in[0];
    const float* px  = (const float*)d_in[1];
    const float* Wq  = (const float*)d_in[2];
    const float* Wk  = (const float*)d_in[3];
    const float* Wv  = (const float*)d_in[4];
    const float* Wo  = (const float*)d_in[5];
    const float* bo  = (const float*)d_in[6];
    const float* Wdw = (const float*)d_in[7];
    const float* bdw = (const float*)d_in[8];
    const float* Wp  = (const float*)d_in[9];
    float* out = (float*)d_out;

    cudaFuncSetAttribute(attn_kernel,
                         cudaFuncAttributeMaxDynamicSharedMemorySize, ABASE + 2 * ABUF);
    cudaFuncSetAttribute(qproj_mma_kernel,
                         cudaFuncAttributeMaxDynamicSharedMemorySize, GP_TOTAL);
    cudaFuncSetAttribute(outproj_mma_kernel,
                         cudaFuncAttributeMaxDynamicSharedMemorySize, GP_TOTAL);

    qproj_mma_kernel<<<dim3(32, 8), 256, GP_TOTAL>>>(x, px, Wq);
    offset_kernel<<<dim3(8, 8), 128>>>(Wdw, bdw, Wp);
    kvproj_mma_kernel<<<dim3(16, 8, 4), 128>>>(x, px, Wk, Wv);
    attn_kernel<<<dim3(32, HEADS, 2), 256, ABASE + 2 * ABUF>>>();
    outproj_mma_kernel<<<dim3(32, 8), 256, GP_TOTAL>>>(Wo, bo, out);
}